// round 16
// baseline (speedup 1.0000x reference)
#include <cuda_runtime.h>
#include <cuda_fp16.h>

// ---------------------------------------------------------------------------
// Problem constants (fixed shapes)
// ---------------------------------------------------------------------------
namespace {
constexpr int B_    = 2;
constexpr int T_    = 12;
constexpr int N_    = 512;     // nodes
constexpr int D_    = 512;     // model dim
constexpr int KH_   = 8;       // heads
constexpr int DH_   = 64;      // head dim
constexpr int DFF_  = 2048;    // ffn hidden
constexpr int BT_   = B_ * T_;         // 24
constexpr int ROWS_ = BT_ * N_;        // 12288 token rows

// fp16 gemm: BK=64 halves (128 B/row), padded row = 36 words (72 halves)
constexpr int GEMM_TILE   = 128 * 36;                       // words per tile
constexpr int GEMM_SMEM   = 3 * 2 * GEMM_TILE * 4;          // 110592 B

// attention smem (32-bit words), 64 queries per block, fp16 operands:
//   Qh 64x36 (fp16, scaled) | S 64x517 fp32 | K stages 2 x 256x36 (fp16)
//   (Vt fp16 64x133 words lives in K buffer 0 during phase 3)
constexpr int ATT_QW   = 64 * 36;       // 2304
constexpr int ATT_SW   = 64 * 517;      // 33088
constexpr int ATT_KW   = 256 * 36;      // 9216 per K buffer
constexpr int ATT_SMEM = (ATT_QW + ATT_SW + 2 * ATT_KW) * 4;  // 215296 B
}

// ---------------------------------------------------------------------------
// Scratch (static device globals: the sanctioned alloc-free scratch path)
// ---------------------------------------------------------------------------
__device__ __align__(16) float  g_x1  [ROWS_ * D_];
__device__ __align__(16) float  g_bias[N_ * N_];
__device__ __align__(16) __half g_xnh [ROWS_ * D_];
__device__ __align__(16) __half g_hh  [ROWS_ * D_];
__device__ __align__(16) __half g_aoh [ROWS_ * D_];
__device__ __align__(16) __half g_hidh[ROWS_ * DFF_];
__device__ __align__(16) __half g_qh  [ROWS_ * D_];
__device__ __align__(16) __half g_kh  [ROWS_ * D_];
__device__ __align__(16) __half g_vh  [ROWS_ * D_];
__device__ __align__(16) __half g_wqh [D_ * D_];
__device__ __align__(16) __half g_wkh [D_ * D_];
__device__ __align__(16) __half g_wvh [D_ * D_];
__device__ __align__(16) __half g_woh [D_ * D_];
__device__ __align__(16) __half g_w1h [DFF_ * D_];
__device__ __align__(16) __half g_w2h [D_ * DFF_];

// ---------------------------------------------------------------------------
// helpers
// ---------------------------------------------------------------------------
__device__ __forceinline__ void cp16(unsigned dst, const void* src) {
    asm volatile("cp.async.cg.shared.global [%0], [%1], 16;\n" :: "r"(dst), "l"(src));
}
__device__ __forceinline__ unsigned packh2(float a, float b) {
    const __half2 h = __floats2half2_rn(a, b);
    return *(const unsigned*)&h;
}
#define MMA_F16(acc, af, bf)                                                   \
    asm volatile(                                                              \
        "mma.sync.aligned.m16n8k16.row.col.f32.f16.f16.f32 "                   \
        "{%0,%1,%2,%3}, {%4,%5,%6,%7}, {%8,%9}, {%0,%1,%2,%3};\n"              \
        : "+f"((acc)[0]), "+f"((acc)[1]), "+f"((acc)[2]), "+f"((acc)[3])       \
        : "r"((af)[0]), "r"((af)[1]), "r"((af)[2]), "r"((af)[3]),              \
          "r"((bf)[0]), "r"((bf)[1]))

// ---------------------------------------------------------------------------
// Kernel 0: fp32 -> fp16 conversion (weights), vectorized, grid-stride
// ---------------------------------------------------------------------------
__global__ void cvt_f2h(const float* __restrict__ s, __half* __restrict__ d, int n4) {
    for (int i = blockIdx.x * blockDim.x + threadIdx.x; i < n4;
         i += gridDim.x * blockDim.x) {
        const float4 v = ((const float4*)s)[i];
        __half2* dp = (__half2*)d + 2 * i;
        dp[0] = __floats2half2_rn(v.x, v.y);
        dp[1] = __floats2half2_rn(v.z, v.w);
    }
}

// ---------------------------------------------------------------------------
// Kernel 1: graph bias  bias[n][m] = a*softmax_row(relu(En.Em)) + b*lap + mask
// ---------------------------------------------------------------------------
__global__ void bias_kernel(const float* __restrict__ E,
                            const float* __restrict__ lap,
                            const float* __restrict__ alphap,
                            const float* __restrict__ betap,
                            float* __restrict__ bias) {
    __shared__ float en[64];
    __shared__ float red[512];
    const int n = blockIdx.x;
    const int t = threadIdx.x;

    if (t < 64) en[t] = E[n * 64 + t];
    __syncthreads();

    const float* em = E + t * 64;
    float acc = 0.f;
#pragma unroll 16
    for (int j = 0; j < 64; j++) acc = fmaf(en[j], em[j], acc);
    float r = fmaxf(acc, 0.f);

    red[t] = r;
    __syncthreads();
    for (int s = 256; s > 0; s >>= 1) {
        if (t < s) red[t] = fmaxf(red[t], red[t + s]);
        __syncthreads();
    }
    const float mx = red[0];
    __syncthreads();

    const float e = __expf(r - mx);
    red[t] = e;
    __syncthreads();
    for (int s = 256; s > 0; s >>= 1) {
        if (t < s) red[t] += red[t + s];
        __syncthreads();
    }
    const float soft = e / red[0];

    const float lv   = lap[n * N_ + t];
    const float mask = (lv == 0.f) ? -1e9f : 0.f;
    bias[n * N_ + t] = (*alphap) * soft + (*betap) * lv + mask;
}

// ---------------------------------------------------------------------------
// Kernel 2: LayerNorm over last dim (512), fp16 output. 128 thr per row.
// ---------------------------------------------------------------------------
__global__ void ln_kernel(const float* __restrict__ x,
                          const float* __restrict__ g,
                          const float* __restrict__ be,
                          __half* __restrict__ y) {
    const int row = blockIdx.x;
    const int t   = threadIdx.x;  // 128
    const float4 v = ((const float4*)(x + (size_t)row * D_))[t];

    float s  = v.x + v.y + v.z + v.w;
    float ss = fmaf(v.x, v.x, fmaf(v.y, v.y, fmaf(v.z, v.z, v.w * v.w)));
#pragma unroll
    for (int o = 16; o; o >>= 1) {
        s  += __shfl_xor_sync(0xffffffffu, s,  o);
        ss += __shfl_xor_sync(0xffffffffu, ss, o);
    }
    __shared__ float sh_s[4], sh_ss[4];
    const int warp = t >> 5, lane = t & 31;
    if (lane == 0) { sh_s[warp] = s; sh_ss[warp] = ss; }
    __syncthreads();
    const float ts  = sh_s[0] + sh_s[1] + sh_s[2] + sh_s[3];
    const float tss = sh_ss[0] + sh_ss[1] + sh_ss[2] + sh_ss[3];

    const float mean = ts * (1.f / 512.f);
    const float var  = tss * (1.f / 512.f) - mean * mean;
    const float inv  = rsqrtf(var + 1e-5f);

    const float4 gv = ((const float4*)g)[t];
    const float4 bv = ((const float4*)be)[t];
    float4 o;
    o.x = (v.x - mean) * inv * gv.x + bv.x;
    o.y = (v.y - mean) * inv * gv.y + bv.y;
    o.z = (v.z - mean) * inv * gv.z + bv.z;
    o.w = (v.w - mean) * inv * gv.w + bv.w;
    __half2* yp = (__half2*)(y + (size_t)row * D_) + t * 2;
    yp[0] = __floats2half2_rn(o.x, o.y);
    yp[1] = __floats2half2_rn(o.z, o.w);
}

// ---------------------------------------------------------------------------
// FP16 tensor-core GEMM NT (verified R15 structure).
// ---------------------------------------------------------------------------
__device__ __forceinline__ void load_frags(const unsigned* __restrict__ Ab,
                                           const unsigned* __restrict__ Bb,
                                           int wm, int wn, int gid, int t4, int ks,
                                           unsigned af[2][4], unsigned bf[8][2]) {
#pragma unroll
    for (int i = 0; i < 2; i++) {
        const unsigned* p = Ab + (wm + 16 * i + gid) * 36 + ks * 8 + t4;
        af[i][0] = p[0]; af[i][1] = p[8 * 36]; af[i][2] = p[4]; af[i][3] = p[8 * 36 + 4];
    }
#pragma unroll
    for (int j = 0; j < 8; j++) {
        const unsigned* p = Bb + (wn + 8 * j + gid) * 36 + ks * 8 + t4;
        bf[j][0] = p[0]; bf[j][1] = p[4];
    }
}

template <bool RELU, bool HAS_RES, bool OUTH>
__device__ __forceinline__
void gemm_body(const __half* __restrict__ A, const __half* __restrict__ W,
               const float* __restrict__ bias, const float* __restrict__ res,
               void* __restrict__ Cv, int Nc, int Kc, float* smf) {
    const int tid  = threadIdx.x;
    const int warp = tid >> 5, lane = tid & 31;
    const int gid  = lane >> 2, t4 = lane & 3;
    const int wm   = (warp & 3) * 32;
    const int wn   = (warp >> 2) * 64;
    const int bm   = blockIdx.y * 128;
    const int bn   = blockIdx.x * 128;
    const int lr   = tid >> 1;          // 0..127
    const int lch  = (tid & 1) * 32;    // 0 or 32 (half index)

    const __half* Ap = A + (size_t)(bm + lr) * Kc + lch;
    const __half* Wp = W + (size_t)(bn + lr) * Kc + lch;
    const unsigned sbase = (unsigned)__cvta_generic_to_shared(smf);
    const unsigned soff  = (unsigned)(lr * 36 + (tid & 1) * 16) * 4u;  // bytes
    const int stages = Kc >> 6;

    float acc[2][8][4];
#pragma unroll
    for (int i = 0; i < 2; i++)
#pragma unroll
        for (int j = 0; j < 8; j++)
#pragma unroll
            for (int c = 0; c < 4; c++) acc[i][j][c] = 0.f;

    // prologue: stages 0,1
#pragma unroll
    for (int s = 0; s < 2; s++) {
        const unsigned da = sbase + (unsigned)(s * 2 * GEMM_TILE) * 4u + soff;
        const unsigned db = da + (unsigned)GEMM_TILE * 4u;
        const __half* a = Ap + s * 64;
        const __half* w = Wp + s * 64;
#pragma unroll
        for (int e = 0; e < 4; e++) { cp16(da + e * 16, a + e * 8); cp16(db + e * 16, w + e * 8); }
        asm volatile("cp.async.commit_group;\n");
    }

    for (int s = 0; s < stages; s++) {
        if (s + 1 < stages) asm volatile("cp.async.wait_group 1;\n");
        else                asm volatile("cp.async.wait_group 0;\n");
        __syncthreads();

        if (s + 2 < stages) {
            const int sn = s + 2;
            const unsigned da = sbase + (unsigned)((sn % 3) * 2 * GEMM_TILE) * 4u + soff;
            const unsigned db = da + (unsigned)GEMM_TILE * 4u;
            const __half* a = Ap + sn * 64;
            const __half* w = Wp + sn * 64;
#pragma unroll
            for (int e = 0; e < 4; e++) { cp16(da + e * 16, a + e * 8); cp16(db + e * 16, w + e * 8); }
            asm volatile("cp.async.commit_group;\n");
        }

        const unsigned* Ab = (const unsigned*)(smf + (s % 3) * 2 * GEMM_TILE);
        const unsigned* Bb = Ab + GEMM_TILE;

        unsigned af[2][2][4], bf[2][8][2];
        load_frags(Ab, Bb, wm, wn, gid, t4, 0, af[0], bf[0]);
#pragma unroll
        for (int ks = 0; ks < 4; ks++) {
            if (ks < 3)
                load_frags(Ab, Bb, wm, wn, gid, t4, ks + 1, af[(ks + 1) & 1], bf[(ks + 1) & 1]);
            const int cur = ks & 1;
#pragma unroll
            for (int i = 0; i < 2; i++)
#pragma unroll
                for (int j = 0; j < 8; j++) MMA_F16(acc[i][j], af[cur][i], bf[cur][j]);
        }
    }

    // epilogue
#pragma unroll
    for (int i = 0; i < 2; i++) {
        const int r0 = bm + wm + 16 * i + gid;
#pragma unroll
        for (int j = 0; j < 8; j++) {
            const int col = bn + wn + 8 * j + 2 * t4;
            const float2 bv = *(const float2*)(bias + col);
            float o00 = acc[i][j][0] + bv.x;
            float o01 = acc[i][j][1] + bv.y;
            float o10 = acc[i][j][2] + bv.x;
            float o11 = acc[i][j][3] + bv.y;
            if (HAS_RES) {
                const float2 rv0 = *(const float2*)(res + (size_t)r0 * Nc + col);
                const float2 rv1 = *(const float2*)(res + (size_t)(r0 + 8) * Nc + col);
                o00 += rv0.x; o01 += rv0.y;
                o10 += rv1.x; o11 += rv1.y;
            }
            if (RELU) {
                o00 = fmaxf(o00, 0.f); o01 = fmaxf(o01, 0.f);
                o10 = fmaxf(o10, 0.f); o11 = fmaxf(o11, 0.f);
            }
            if (OUTH) {
                __half* C = (__half*)Cv;
                *(__half2*)(C + (size_t)r0 * Nc + col)       = __floats2half2_rn(o00, o01);
                *(__half2*)(C + (size_t)(r0 + 8) * Nc + col) = __floats2half2_rn(o10, o11);
            } else {
                float* C = (float*)Cv;
                *(float2*)(C + (size_t)r0 * Nc + col)       = make_float2(o00, o01);
                *(float2*)(C + (size_t)(r0 + 8) * Nc + col) = make_float2(o10, o11);
            }
        }
    }
}

template <bool RELU, bool HAS_RES, bool OUTH>
__global__ __launch_bounds__(256, 2)
void gemm_tc(const __half* __restrict__ A, const __half* __restrict__ W,
             const float* __restrict__ bias, const float* __restrict__ res,
             void* __restrict__ C, int Nc, int Kc) {
    extern __shared__ float smf[];
    gemm_body<RELU, HAS_RES, OUTH>(A, W, bias, res, C, Nc, Kc, smf);
}

// fused QKV: blockIdx.z selects weight/bias/output; fp16 outputs
struct QKVArgs {
    const __half* W[3];
    const float*  b[3];
    __half*       o[3];
};
__global__ __launch_bounds__(256, 2)
void gemm_qkv(const __half* __restrict__ A, QKVArgs args) {
    extern __shared__ float smf[];
    const int z = blockIdx.z;
    gemm_body<false, false, true>(A, args.W[z], args.b[z], nullptr, args.o[z], D_, D_, smf);
}

// ---------------------------------------------------------------------------
// Kernel 4: fp16 tensor-core attention. block = (head, 64-query tile), 256 thr.
// Phase1: S = Qh Kh^T + bias (fp16 m16n8k16, gemm-verified stride-36 frags,
//         K double-buffered cp.async). Phase2: exact fp32 softmax in S.
// Phase3: O = P V; P packed fp32->fp16 on the fly; Vt staged fp16 transposed.
// ---------------------------------------------------------------------------
__global__ __launch_bounds__(256)
void attn_tc(const __half* __restrict__ Q, const __half* __restrict__ Kx,
             const __half* __restrict__ V, const float* __restrict__ bias,
             __half* __restrict__ O) {
    extern __shared__ float sm[];
    unsigned* Qu  = (unsigned*)sm;          // 64 x 36 words (fp16, scaled)
    float*    S   = sm + ATT_QW;            // 64 x 517 fp32
    unsigned* STu = (unsigned*)(S + ATT_SW);// K buffers / Vt (fp16)
    __half*   STh = (__half*)STu;

    const int tid  = threadIdx.x;
    const int warp = tid >> 5, lane = tid & 31;
    const int gid  = lane >> 2, t4 = lane & 3;
    const int hidx = blockIdx.y;        // 0..191
    const int bt   = hidx >> 3;
    const int kh   = hidx & 7;
    const int n0   = blockIdx.x * 64;
    const size_t rowbase = (size_t)bt * N_;
    const size_t headoff = (size_t)kh * DH_;
    const unsigned stbase = (unsigned)__cvta_generic_to_shared(STu);

    // load Q tile (64 x 64 halves), scale by 1/sqrt(64)=0.125
    {
        const __half2 sc = __float2half2_rn(0.125f);
        for (int i = tid; i < 64 * 8; i += 256) {
            const int r = i >> 3, wg = i & 7;           // wg: 4-word group
            const uint4 hv = *(const uint4*)(Q + (rowbase + n0 + r) * D_ + headoff + wg * 8);
            uint4 o;
            __half2 h;
            h = __hmul2(*(const __half2*)&hv.x, sc); o.x = *(unsigned*)&h;
            h = __hmul2(*(const __half2*)&hv.y, sc); o.y = *(unsigned*)&h;
            h = __hmul2(*(const __half2*)&hv.z, sc); o.z = *(unsigned*)&h;
            h = __hmul2(*(const __half2*)&hv.w, sc); o.w = *(unsigned*)&h;
            *(uint4*)(Qu + r * 36 + wg * 4) = o;
        }
    }

    // prefetch both K chunks (fp16, 128 B per key row = 8 cp16)
#pragma unroll
    for (int ch = 0; ch < 2; ch++) {
        const unsigned kb = stbase + (unsigned)(ch * ATT_KW) * 4u;
        for (int i = tid; i < 256 * 8; i += 256) {
            const int r = i >> 3, e = i & 7;
            cp16(kb + (unsigned)(r * 36 + e * 4) * 4u,
                 Kx + (rowbase + ch * 256 + r) * D_ + headoff + e * 8);
        }
        asm volatile("cp.async.commit_group;\n");
    }

    // ---- phase 1: S = Q K^T + bias (2 chunks of 256 keys, fp16 mma) ------
    const int wq = (warp & 1) * 32;     // query tile base
    const int wk = (warp >> 1) * 64;    // key base within chunk
    for (int ch = 0; ch < 2; ch++) {
        if (ch == 0) asm volatile("cp.async.wait_group 1;\n");
        else         asm volatile("cp.async.wait_group 0;\n");
        __syncthreads();
        const unsigned* Kb = STu + ch * ATT_KW;
        const int m0 = ch * 256;

        float acc[2][8][4];
#pragma unroll
        for (int i = 0; i < 2; i++)
#pragma unroll
            for (int j = 0; j < 8; j++)
#pragma unroll
                for (int c = 0; c < 4; c++) acc[i][j][c] = 0.f;

#pragma unroll
        for (int ks = 0; ks < 4; ks++) {
            unsigned af[2][4], bf[8][2];
#pragma unroll
            for (int i = 0; i < 2; i++) {
                const unsigned* p = Qu + (wq + 16 * i + gid) * 36 + ks * 8 + t4;
                af[i][0] = p[0]; af[i][1] = p[8 * 36]; af[i][2] = p[4]; af[i][3] = p[8 * 36 + 4];
            }
#pragma unroll
            for (int j = 0; j < 8; j++) {
                const unsigned* p = Kb + (wk + 8 * j + gid) * 36 + ks * 8 + t4;
                bf[j][0] = p[0]; bf[j][1] = p[4];
            }
#pragma unroll
            for (int i = 0; i < 2; i++)
#pragma unroll
                for (int j = 0; j < 8; j++) MMA_F16(acc[i][j], af[i], bf[j]);
        }

        // store S (+bias)
#pragma unroll
        for (int i = 0; i < 2; i++) {
            const int r0 = wq + 16 * i + gid;
#pragma unroll
            for (int j = 0; j < 8; j++) {
                const int col = wk + 8 * j + 2 * t4;      // within chunk
                const float2 b0 = *(const float2*)(bias + (size_t)(n0 + r0) * N_ + m0 + col);
                const float2 b1 = *(const float2*)(bias + (size_t)(n0 + r0 + 8) * N_ + m0 + col);
                S[r0 * 517 + m0 + col]           = acc[i][j][0] + b0.x;
                S[r0 * 517 + m0 + col + 1]       = acc[i][j][1] + b0.y;
                S[(r0 + 8) * 517 + m0 + col]     = acc[i][j][2] + b1.x;
                S[(r0 + 8) * 517 + m0 + col + 1] = acc[i][j][3] + b1.y;
            }
        }
    }
    __syncthreads();

    // ---- phase 2: exact row softmax (fp32 in S) ---------------------------
    {
#pragma unroll
        for (int ii = 0; ii < 8; ii++) {
            float* row = S + (warp * 8 + ii) * 517;
            float mx = -3.4e38f;
            for (int m = lane; m < N_; m += 32) mx = fmaxf(mx, row[m]);
#pragma unroll
            for (int o = 16; o; o >>= 1) mx = fmaxf(mx, __shfl_xor_sync(0xffffffffu, mx, o));
            float sum = 0.f;
            for (int m = lane; m < N_; m += 32) {
                const float e = __expf(row[m] - mx);
                row[m] = e;
                sum += e;
            }
#pragma unroll
            for (int o = 16; o; o >>= 1) sum += __shfl_xor_sync(0xffffffffu, sum, o);
            const float inv = 1.f / sum;
            for (int m = lane; m < N_; m += 32) row[m] *= inv;
        }
    }

    // ---- phase 3: O = P V (fp16 mma; P packed on the fly, Vt fp16) -------
    const int wq3 = (warp & 1) * 32;    // query tile base
    const int kg  = warp >> 1;          // 0..3: 64-key group within chunk
    float acc3[2][8][4];
#pragma unroll
    for (int i = 0; i < 2; i++)
#pragma unroll
        for (int j = 0; j < 8; j++)
#pragma unroll
            for (int c = 0; c < 4; c++) acc3[i][j][c] = 0.f;

    for (int ch = 0; ch < 2; ch++) {
        const int m0 = ch * 256;
        __syncthreads();
        // stage Vt[d][key] fp16, stride 266 halves (133 words)
        for (int i = tid; i < 256 * 8; i += 256) {
            const int r = i >> 3, cg = (i & 7) * 8;    // r = key, cg = d base
            const uint4 vv = *(const uint4*)(V + (rowbase + m0 + r) * D_ + headoff + cg);
            __half ha[8];
            *(uint4*)ha = vv;
#pragma unroll
            for (int t = 0; t < 8; t++) STh[(cg + t) * 266 + r] = ha[t];
        }
        __syncthreads();

#pragma unroll
        for (int ks = 0; ks < 4; ks++) {
            unsigned af[2][4], bf[8][2];
#pragma unroll
            for (int i = 0; i < 2; i++) {
                const float* s0 = S + (wq3 + 16 * i + gid) * 517 + m0 + kg * 64 + ks * 16;
                const float* s1 = s0 + 8 * 517;
                af[i][0] = packh2(s0[2 * t4],     s0[2 * t4 + 1]);
                af[i][1] = packh2(s1[2 * t4],     s1[2 * t4 + 1]);
                af[i][2] = packh2(s0[2 * t4 + 8], s0[2 * t4 + 9]);
                af[i][3] = packh2(s1[2 * t4 + 8], s1[2 * t4 + 9]);
            }
#pragma unroll
            for (int j = 0; j < 8; j++) {
                const unsigned* p = STu + (8 * j + gid) * 133 + kg * 32 + ks * 8 + t4;
                bf[j][0] = p[0]; bf[j][1] = p[4];
            }
#pragma unroll
            for (int i = 0; i < 2; i++)
#pragma unroll
                for (int j = 0; j < 8; j++) MMA_F16(acc3[i][j], af[i], bf[j]);
        }
    }

    // reduce the 4 k-split partials through smem (reuse S region, stride 68)
    __syncthreads();
    {
        float* part = S + warp * (32 * 68);
#pragma unroll
        for (int i = 0; i < 2; i++) {
            const int r = 16 * i + gid;
#pragma unroll
            for (int j = 0; j < 8; j++) {
                const int c = 8 * j + 2 * t4;
                *(float2*)(part + r * 68 + c)       = make_float2(acc3[i][j][0], acc3[i][j][1]);
                *(float2*)(part + (r + 8) * 68 + c) = make_float2(acc3[i][j][2], acc3[i][j][3]);
            }
        }
    }
    __syncthreads();

    // sum over kg and write O (fp16)
    for (int i = tid; i < 64 * 16; i += 256) {
        const int q  = i >> 4, dc = (i & 15) << 2;
        const int mt = q >> 5, qi = q & 31;
        float4 o = make_float4(0.f, 0.f, 0.f, 0.f);
#pragma unroll
        for (int kg2 = 0; kg2 < 4; kg2++) {
            const float4 p = *(const float4*)(S + (kg2 * 2 + mt) * (32 * 68) + qi * 68 + dc);
            o.x += p.x; o.y += p.y; o.z += p.z; o.w += p.w;
        }
        __half2* op = (__half2*)(O + (rowbase + n0 + q) * D_ + headoff + dc);
        op[0] = __floats2half2_rn(o.x, o.y);
        op[1] = __floats2half2_rn(o.z, o.w);
    }
}

// ---------------------------------------------------------------------------
// Launch
// ---------------------------------------------------------------------------
extern "C" void kernel_launch(void* const* d_in, const int* in_sizes, int n_in,
                              void* d_out, int out_size) {
    (void)in_sizes; (void)n_in; (void)out_size;
    const float* x    = (const float*)d_in[0];
    const float* lap  = (const float*)d_in[1];
    const float* ne   = (const float*)d_in[2];
    const float* Wq   = (const float*)d_in[3];
    const float* bq   = (const float*)d_in[4];
    const float* Wk   = (const float*)d_in[5];
    const float* bk   = (const float*)d_in[6];
    const float* Wv   = (const float*)d_in[7];
    const float* bv   = (const float*)d_in[8];
    const float* Wo   = (const float*)d_in[9];
    const float* bo   = (const float*)d_in[10];
    const float* W1   = (const float*)d_in[11];
    const float* b1   = (const float*)d_in[12];
    const float* W2   = (const float*)d_in[13];
    const float* b2   = (const float*)d_in[14];
    const float* g1   = (const float*)d_in[15];
    const float* be1  = (const float*)d_in[16];
    const float* g2   = (const float*)d_in[17];
    const float* be2  = (const float*)d_in[18];
    const float* alp  = (const float*)d_in[19];
    const float* bet  = (const float*)d_in[20];
    float* out = (float*)d_out;

    float *x1, *bias;
    __half *xnh, *hh, *aoh, *hidh, *qh, *kh, *vh;
    __half *wqh, *wkh, *wvh, *woh, *w1h, *w2h;
    cudaGetSymbolAddress((void**)&x1,   g_x1);
    cudaGetSymbolAddress((void**)&bias, g_bias);
    cudaGetSymbolAddress((void**)&xnh,  g_xnh);
    cudaGetSymbolAddress((void**)&hh,   g_hh);
    cudaGetSymbolAddress((void**)&aoh,  g_aoh);
    cudaGetSymbolAddress((void**)&hidh, g_hidh);
    cudaGetSymbolAddress((void**)&qh,   g_qh);
    cudaGetSymbolAddress((void**)&kh,   g_kh);
    cudaGetSymbolAddress((void**)&vh,   g_vh);
    cudaGetSymbolAddress((void**)&wqh,  g_wqh);
    cudaGetSymbolAddress((void**)&wkh,  g_wkh);
    cudaGetSymbolAddress((void**)&wvh,  g_wvh);
    cudaGetSymbolAddress((void**)&woh,  g_woh);
    cudaGetSymbolAddress((void**)&w1h,  g_w1h);
    cudaGetSymbolAddress((void**)&w2h,  g_w2h);

    cudaFuncSetAttribute(attn_tc,
                         cudaFuncAttributeMaxDynamicSharedMemorySize, ATT_SMEM);
    cudaFuncSetAttribute(gemm_qkv,
                         cudaFuncAttributeMaxDynamicSharedMemorySize, GEMM_SMEM);
    cudaFuncSetAttribute(gemm_tc<false, true, false>,
                         cudaFuncAttributeMaxDynamicSharedMemorySize, GEMM_SMEM);
    cudaFuncSetAttribute(gemm_tc<true, false, true>,
                         cudaFuncAttributeMaxDynamicSharedMemorySize, GEMM_SMEM);

    // 0) weights -> fp16
    cvt_f2h<<<256, 256>>>(Wq, wqh, D_ * D_ / 4);
    cvt_f2h<<<256, 256>>>(Wk, wkh, D_ * D_ / 4);
    cvt_f2h<<<256, 256>>>(Wv, wvh, D_ * D_ / 4);
    cvt_f2h<<<256, 256>>>(Wo, woh, D_ * D_ / 4);
    cvt_f2h<<<512, 256>>>(W1, w1h, DFF_ * D_ / 4);
    cvt_f2h<<<512, 256>>>(W2, w2h, D_ * DFF_ / 4);

    // 1) graph bias (b,t,k-invariant)
    bias_kernel<<<N_, N_>>>(ne, lap, alp, bet, bias);

    // 2) LN1 -> fp16
    ln_kernel<<<ROWS_, 128>>>(x, g1, be1, xnh);

    // 3) Q/K/V projections — fused single launch, fp16 in/out
    const dim3 thr(256);
    QKVArgs qa;
    qa.W[0] = wqh; qa.W[1] = wkh; qa.W[2] = wvh;
    qa.b[0] = bq;  qa.b[1] = bk;  qa.b[2] = bv;
    qa.o[0] = qh;  qa.o[1] = kh;  qa.o[2] = vh;
    gemm_qkv<<<dim3(D_ / 128, ROWS_ / 128, 3), thr, GEMM_SMEM>>>(xnh, qa);

    // 4) attention (192 heads x 8 query tiles) -> fp16 ao
    attn_tc<<<dim3(N_ / 64, BT_ * KH_), thr, ATT_SMEM>>>(qh, kh, vh, bias, aoh);

    // 5) output projection + residual (x) -> fp32 x1
    gemm_tc<false, true, false><<<dim3(D_ / 128, ROWS_ / 128), thr, GEMM_SMEM>>>(
        aoh, woh, bo, x, x1, D_, D_);

    // 6) LN2 -> fp16
    ln_kernel<<<ROWS_, 128>>>(x1, g2, be2, hh);

    // 7) FFN1 with fused ReLU -> fp16 hid
    gemm_tc<true, false, true><<<dim3(DFF_ / 128, ROWS_ / 128), thr, GEMM_SMEM>>>(
        hh, w1h, b1, nullptr, hidh, DFF_, D_);

    // 8) FFN2 + residual (x1) -> fp32 output
    gemm_tc<false, true, false><<<dim3(D_ / 128, ROWS_ / 128), thr, GEMM_SMEM>>>(
        hidh, w2h, b2, x1, out, D_, DFF_);
}

// round 17
// speedup vs baseline: 1.4480x; 1.4480x over previous
#include <cuda_runtime.h>
#include <cuda_fp16.h>

// ---------------------------------------------------------------------------
// Problem constants (fixed shapes)
// ---------------------------------------------------------------------------
namespace {
constexpr int B_    = 2;
constexpr int T_    = 12;
constexpr int N_    = 512;     // nodes
constexpr int D_    = 512;     // model dim
constexpr int KH_   = 8;       // heads
constexpr int DH_   = 64;      // head dim
constexpr int DFF_  = 2048;    // ffn hidden
constexpr int BT_   = B_ * T_;         // 24
constexpr int ROWS_ = BT_ * N_;        // 12288 token rows

// fp16 gemm: BK=64 halves (128 B/row), padded row = 36 words (72 halves)
constexpr int GEMM_TILE   = 128 * 36;                       // words per tile
constexpr int GEMM_SMEM   = 3 * 2 * GEMM_TILE * 4;          // 110592 B

// attention smem (32-bit words), 64 queries per block:
//   Qh 64x36 (fp16, scaled) | S 64x517 fp32 | stage: 2 x 256x36 K fp16
//   (Vt tf32 64x261 = 16704 words reuses the 18432-word stage region)
constexpr int ATT_QW   = 64 * 36;       // 2304
constexpr int ATT_SW   = 64 * 517;      // 33088
constexpr int ATT_KW   = 256 * 36;      // 9216 per K buffer
constexpr int ATT_SMEM = (ATT_QW + ATT_SW + 2 * ATT_KW) * 4;  // 215296 B
}

// ---------------------------------------------------------------------------
// Scratch (static device globals: the sanctioned alloc-free scratch path)
// ---------------------------------------------------------------------------
__device__ __align__(16) float  g_v   [ROWS_ * D_];
__device__ __align__(16) float  g_x1  [ROWS_ * D_];
__device__ __align__(16) float  g_bias[N_ * N_];
__device__ __align__(16) __half g_xnh [ROWS_ * D_];
__device__ __align__(16) __half g_hh  [ROWS_ * D_];
__device__ __align__(16) __half g_aoh [ROWS_ * D_];
__device__ __align__(16) __half g_hidh[ROWS_ * DFF_];
__device__ __align__(16) __half g_qh  [ROWS_ * D_];
__device__ __align__(16) __half g_kh  [ROWS_ * D_];
__device__ __align__(16) __half g_wqh [D_ * D_];
__device__ __align__(16) __half g_wkh [D_ * D_];
__device__ __align__(16) __half g_wvh [D_ * D_];
__device__ __align__(16) __half g_woh [D_ * D_];
__device__ __align__(16) __half g_w1h [DFF_ * D_];
__device__ __align__(16) __half g_w2h [D_ * DFF_];

// ---------------------------------------------------------------------------
// helpers
// ---------------------------------------------------------------------------
__device__ __forceinline__ unsigned f2tf32(float x) {
    unsigned r;
    asm("cvt.rna.tf32.f32 %0, %1;" : "=r"(r) : "f"(x));
    return r;
}
__device__ __forceinline__ void cp16(unsigned dst, const void* src) {
    asm volatile("cp.async.cg.shared.global [%0], [%1], 16;\n" :: "r"(dst), "l"(src));
}
#define MMA_F16(acc, af, bf)                                                   \
    asm volatile(                                                              \
        "mma.sync.aligned.m16n8k16.row.col.f32.f16.f16.f32 "                   \
        "{%0,%1,%2,%3}, {%4,%5,%6,%7}, {%8,%9}, {%0,%1,%2,%3};\n"              \
        : "+f"((acc)[0]), "+f"((acc)[1]), "+f"((acc)[2]), "+f"((acc)[3])       \
        : "r"((af)[0]), "r"((af)[1]), "r"((af)[2]), "r"((af)[3]),              \
          "r"((bf)[0]), "r"((bf)[1]))
#define MMA_TF32(acc, af, bf)                                                  \
    asm volatile(                                                              \
        "mma.sync.aligned.m16n8k8.row.col.f32.tf32.tf32.f32 "                  \
        "{%0,%1,%2,%3}, {%4,%5,%6,%7}, {%8,%9}, {%0,%1,%2,%3};\n"              \
        : "+f"((acc)[0]), "+f"((acc)[1]), "+f"((acc)[2]), "+f"((acc)[3])       \
        : "r"((af)[0]), "r"((af)[1]), "r"((af)[2]), "r"((af)[3]),              \
          "r"((bf)[0]), "r"((bf)[1]))

// ---------------------------------------------------------------------------
// Kernel 0: fp32 -> fp16 conversion (weights), vectorized, grid-stride
// ---------------------------------------------------------------------------
__global__ void cvt_f2h(const float* __restrict__ s, __half* __restrict__ d, int n4) {
    for (int i = blockIdx.x * blockDim.x + threadIdx.x; i < n4;
         i += gridDim.x * blockDim.x) {
        const float4 v = ((const float4*)s)[i];
        __half2* dp = (__half2*)d + 2 * i;
        dp[0] = __floats2half2_rn(v.x, v.y);
        dp[1] = __floats2half2_rn(v.z, v.w);
    }
}

// ---------------------------------------------------------------------------
// Kernel 1: graph bias  bias[n][m] = a*softmax_row(relu(En.Em)) + b*lap + mask
// ---------------------------------------------------------------------------
__global__ void bias_kernel(const float* __restrict__ E,
                            const float* __restrict__ lap,
                            const float* __restrict__ alphap,
                            const float* __restrict__ betap,
                            float* __restrict__ bias) {
    __shared__ float en[64];
    __shared__ float red[512];
    const int n = blockIdx.x;
    const int t = threadIdx.x;

    if (t < 64) en[t] = E[n * 64 + t];
    __syncthreads();

    const float* em = E + t * 64;
    float acc = 0.f;
#pragma unroll 16
    for (int j = 0; j < 64; j++) acc = fmaf(en[j], em[j], acc);
    float r = fmaxf(acc, 0.f);

    red[t] = r;
    __syncthreads();
    for (int s = 256; s > 0; s >>= 1) {
        if (t < s) red[t] = fmaxf(red[t], red[t + s]);
        __syncthreads();
    }
    const float mx = red[0];
    __syncthreads();

    const float e = __expf(r - mx);
    red[t] = e;
    __syncthreads();
    for (int s = 256; s > 0; s >>= 1) {
        if (t < s) red[t] += red[t + s];
        __syncthreads();
    }
    const float soft = e / red[0];

    const float lv   = lap[n * N_ + t];
    const float mask = (lv == 0.f) ? -1e9f : 0.f;
    bias[n * N_ + t] = (*alphap) * soft + (*betap) * lv + mask;
}

// ---------------------------------------------------------------------------
// Kernel 2: LayerNorm over last dim (512), fp16 output. 128 thr per row.
// ---------------------------------------------------------------------------
__global__ void ln_kernel(const float* __restrict__ x,
                          const float* __restrict__ g,
                          const float* __restrict__ be,
                          __half* __restrict__ y) {
    const int row = blockIdx.x;
    const int t   = threadIdx.x;  // 128
    const float4 v = ((const float4*)(x + (size_t)row * D_))[t];

    float s  = v.x + v.y + v.z + v.w;
    float ss = fmaf(v.x, v.x, fmaf(v.y, v.y, fmaf(v.z, v.z, v.w * v.w)));
#pragma unroll
    for (int o = 16; o; o >>= 1) {
        s  += __shfl_xor_sync(0xffffffffu, s,  o);
        ss += __shfl_xor_sync(0xffffffffu, ss, o);
    }
    __shared__ float sh_s[4], sh_ss[4];
    const int warp = t >> 5, lane = t & 31;
    if (lane == 0) { sh_s[warp] = s; sh_ss[warp] = ss; }
    __syncthreads();
    const float ts  = sh_s[0] + sh_s[1] + sh_s[2] + sh_s[3];
    const float tss = sh_ss[0] + sh_ss[1] + sh_ss[2] + sh_ss[3];

    const float mean = ts * (1.f / 512.f);
    const float var  = tss * (1.f / 512.f) - mean * mean;
    const float inv  = rsqrtf(var + 1e-5f);

    const float4 gv = ((const float4*)g)[t];
    const float4 bv = ((const float4*)be)[t];
    float4 o;
    o.x = (v.x - mean) * inv * gv.x + bv.x;
    o.y = (v.y - mean) * inv * gv.y + bv.y;
    o.z = (v.z - mean) * inv * gv.z + bv.z;
    o.w = (v.w - mean) * inv * gv.w + bv.w;
    __half2* yp = (__half2*)(y + (size_t)row * D_) + t * 2;
    yp[0] = __floats2half2_rn(o.x, o.y);
    yp[1] = __floats2half2_rn(o.z, o.w);
}

// ---------------------------------------------------------------------------
// FP16 tensor-core GEMM NT (verified R15 structure).
// ---------------------------------------------------------------------------
__device__ __forceinline__ void load_frags(const unsigned* __restrict__ Ab,
                                           const unsigned* __restrict__ Bb,
                                           int wm, int wn, int gid, int t4, int ks,
                                           unsigned af[2][4], unsigned bf[8][2]) {
#pragma unroll
    for (int i = 0; i < 2; i++) {
        const unsigned* p = Ab + (wm + 16 * i + gid) * 36 + ks * 8 + t4;
        af[i][0] = p[0]; af[i][1] = p[8 * 36]; af[i][2] = p[4]; af[i][3] = p[8 * 36 + 4];
    }
#pragma unroll
    for (int j = 0; j < 8; j++) {
        const unsigned* p = Bb + (wn + 8 * j + gid) * 36 + ks * 8 + t4;
        bf[j][0] = p[0]; bf[j][1] = p[4];
    }
}

template <bool RELU, bool HAS_RES, bool OUTH>
__device__ __forceinline__
void gemm_body(const __half* __restrict__ A, const __half* __restrict__ W,
               const float* __restrict__ bias, const float* __restrict__ res,
               void* __restrict__ Cv, int Nc, int Kc, float* smf) {
    const int tid  = threadIdx.x;
    const int warp = tid >> 5, lane = tid & 31;
    const int gid  = lane >> 2, t4 = lane & 3;
    const int wm   = (warp & 3) * 32;
    const int wn   = (warp >> 2) * 64;
    const int bm   = blockIdx.y * 128;
    const int bn   = blockIdx.x * 128;
    const int lr   = tid >> 1;          // 0..127
    const int lch  = (tid & 1) * 32;    // 0 or 32 (half index)

    const __half* Ap = A + (size_t)(bm + lr) * Kc + lch;
    const __half* Wp = W + (size_t)(bn + lr) * Kc + lch;
    const unsigned sbase = (unsigned)__cvta_generic_to_shared(smf);
    const unsigned soff  = (unsigned)(lr * 36 + (tid & 1) * 16) * 4u;  // bytes
    const int stages = Kc >> 6;

    float acc[2][8][4];
#pragma unroll
    for (int i = 0; i < 2; i++)
#pragma unroll
        for (int j = 0; j < 8; j++)
#pragma unroll
            for (int c = 0; c < 4; c++) acc[i][j][c] = 0.f;

    // prologue: stages 0,1
#pragma unroll
    for (int s = 0; s < 2; s++) {
        const unsigned da = sbase + (unsigned)(s * 2 * GEMM_TILE) * 4u + soff;
        const unsigned db = da + (unsigned)GEMM_TILE * 4u;
        const __half* a = Ap + s * 64;
        const __half* w = Wp + s * 64;
#pragma unroll
        for (int e = 0; e < 4; e++) { cp16(da + e * 16, a + e * 8); cp16(db + e * 16, w + e * 8); }
        asm volatile("cp.async.commit_group;\n");
    }

    for (int s = 0; s < stages; s++) {
        if (s + 1 < stages) asm volatile("cp.async.wait_group 1;\n");
        else                asm volatile("cp.async.wait_group 0;\n");
        __syncthreads();

        if (s + 2 < stages) {
            const int sn = s + 2;
            const unsigned da = sbase + (unsigned)((sn % 3) * 2 * GEMM_TILE) * 4u + soff;
            const unsigned db = da + (unsigned)GEMM_TILE * 4u;
            const __half* a = Ap + sn * 64;
            const __half* w = Wp + sn * 64;
#pragma unroll
            for (int e = 0; e < 4; e++) { cp16(da + e * 16, a + e * 8); cp16(db + e * 16, w + e * 8); }
            asm volatile("cp.async.commit_group;\n");
        }

        const unsigned* Ab = (const unsigned*)(smf + (s % 3) * 2 * GEMM_TILE);
        const unsigned* Bb = Ab + GEMM_TILE;

        unsigned af[2][2][4], bf[2][8][2];
        load_frags(Ab, Bb, wm, wn, gid, t4, 0, af[0], bf[0]);
#pragma unroll
        for (int ks = 0; ks < 4; ks++) {
            if (ks < 3)
                load_frags(Ab, Bb, wm, wn, gid, t4, ks + 1, af[(ks + 1) & 1], bf[(ks + 1) & 1]);
            const int cur = ks & 1;
#pragma unroll
            for (int i = 0; i < 2; i++)
#pragma unroll
                for (int j = 0; j < 8; j++) MMA_F16(acc[i][j], af[cur][i], bf[cur][j]);
        }
    }

    // epilogue
#pragma unroll
    for (int i = 0; i < 2; i++) {
        const int r0 = bm + wm + 16 * i + gid;
#pragma unroll
        for (int j = 0; j < 8; j++) {
            const int col = bn + wn + 8 * j + 2 * t4;
            const float2 bv = *(const float2*)(bias + col);
            float o00 = acc[i][j][0] + bv.x;
            float o01 = acc[i][j][1] + bv.y;
            float o10 = acc[i][j][2] + bv.x;
            float o11 = acc[i][j][3] + bv.y;
            if (HAS_RES) {
                const float2 rv0 = *(const float2*)(res + (size_t)r0 * Nc + col);
                const float2 rv1 = *(const float2*)(res + (size_t)(r0 + 8) * Nc + col);
                o00 += rv0.x; o01 += rv0.y;
                o10 += rv1.x; o11 += rv1.y;
            }
            if (RELU) {
                o00 = fmaxf(o00, 0.f); o01 = fmaxf(o01, 0.f);
                o10 = fmaxf(o10, 0.f); o11 = fmaxf(o11, 0.f);
            }
            if (OUTH) {
                __half* C = (__half*)Cv;
                *(__half2*)(C + (size_t)r0 * Nc + col)       = __floats2half2_rn(o00, o01);
                *(__half2*)(C + (size_t)(r0 + 8) * Nc + col) = __floats2half2_rn(o10, o11);
            } else {
                float* C = (float*)Cv;
                *(float2*)(C + (size_t)r0 * Nc + col)       = make_float2(o00, o01);
                *(float2*)(C + (size_t)(r0 + 8) * Nc + col) = make_float2(o10, o11);
            }
        }
    }
}

template <bool RELU, bool HAS_RES, bool OUTH>
__global__ __launch_bounds__(256, 2)
void gemm_tc(const __half* __restrict__ A, const __half* __restrict__ W,
             const float* __restrict__ bias, const float* __restrict__ res,
             void* __restrict__ C, int Nc, int Kc) {
    extern __shared__ float smf[];
    gemm_body<RELU, HAS_RES, OUTH>(A, W, bias, res, C, Nc, Kc, smf);
}

// fused QKV: z=0,1 (Q,K) write fp16; z=2 (V) writes fp32
struct QKVArgs {
    const __half* W[3];
    const float*  b[3];
    __half*       oh[2];
    float*        of;
};
__global__ __launch_bounds__(256, 2)
void gemm_qkv(const __half* __restrict__ A, QKVArgs args) {
    extern __shared__ float smf[];
    const int z = blockIdx.z;
    if (z == 2)
        gemm_body<false, false, false>(A, args.W[2], args.b[2], nullptr, args.of, D_, D_, smf);
    else
        gemm_body<false, false, true>(A, args.W[z], args.b[z], nullptr, args.oh[z], D_, D_, smf);
}

// ---------------------------------------------------------------------------
// Kernel 4: attention. block = (head, 64-query tile), 256 thr.
// Phase1: fp16 m16n8k16 (GEMM-verified stride-36 frags; K cp.async
//         double-buffered, both chunks prefetched). Q,K fp16 from QKV GEMM.
// Phase2: exact fp32 softmax; P rewritten RNA tf32 (verified R15).
// Phase3: tf32 PV, Vt staged transposed from fp32 V (verified R15, unchanged).
// ---------------------------------------------------------------------------
__global__ __launch_bounds__(256)
void attn_tc(const __half* __restrict__ Q, const __half* __restrict__ Kx,
             const float* __restrict__ V, const float* __restrict__ bias,
             __half* __restrict__ O) {
    extern __shared__ float sm[];
    unsigned* Qu  = (unsigned*)sm;          // 64 x 36 words (fp16, scaled)
    float*    S   = sm + ATT_QW;            // 64 x 517 fp32
    unsigned* STu = (unsigned*)(S + ATT_SW);// K fp16 buffers / Vt tf32
    unsigned* Su  = (unsigned*)S;

    const int tid  = threadIdx.x;
    const int warp = tid >> 5, lane = tid & 31;
    const int gid  = lane >> 2, t4 = lane & 3;
    const int hidx = blockIdx.y;        // 0..191
    const int bt   = hidx >> 3;
    const int kh   = hidx & 7;
    const int n0   = blockIdx.x * 64;
    const size_t rowbase = (size_t)bt * N_;
    const size_t headoff = (size_t)kh * DH_;
    const unsigned stbase = (unsigned)__cvta_generic_to_shared(STu);

    // load Q tile (64 x 64 halves), scale by 1/sqrt(64)=0.125
    {
        const __half2 sc = __float2half2_rn(0.125f);
        for (int i = tid; i < 64 * 8; i += 256) {
            const int r = i >> 3, wg = i & 7;           // wg: 4-word group
            const uint4 hv = *(const uint4*)(Q + (rowbase + n0 + r) * D_ + headoff + wg * 8);
            uint4 o;
            __half2 h;
            h = __hmul2(*(const __half2*)&hv.x, sc); o.x = *(unsigned*)&h;
            h = __hmul2(*(const __half2*)&hv.y, sc); o.y = *(unsigned*)&h;
            h = __hmul2(*(const __half2*)&hv.z, sc); o.z = *(unsigned*)&h;
            h = __hmul2(*(const __half2*)&hv.w, sc); o.w = *(unsigned*)&h;
            *(uint4*)(Qu + r * 36 + wg * 4) = o;
        }
    }

    // prefetch both K chunks (fp16, 128 B per key row = 8 cp16)
#pragma unroll
    for (int ch = 0; ch < 2; ch++) {
        const unsigned kb = stbase + (unsigned)(ch * ATT_KW) * 4u;
        for (int i = tid; i < 256 * 8; i += 256) {
            const int r = i >> 3, e = i & 7;
            cp16(kb + (unsigned)(r * 36 + e * 4) * 4u,
                 Kx + (rowbase + ch * 256 + r) * D_ + headoff + e * 8);
        }
        asm volatile("cp.async.commit_group;\n");
    }

    // ---- phase 1: S = Q K^T + bias (2 chunks of 256 keys, fp16 mma) ------
    const int wq = (warp & 1) * 32;     // query tile base
    const int wk = (warp >> 1) * 64;    // key base within chunk
    for (int ch = 0; ch < 2; ch++) {
        if (ch == 0) asm volatile("cp.async.wait_group 1;\n");
        else         asm volatile("cp.async.wait_group 0;\n");
        __syncthreads();
        const unsigned* Kb = STu + ch * ATT_KW;
        const int m0 = ch * 256;

        float acc[2][8][4];
#pragma unroll
        for (int i = 0; i < 2; i++)
#pragma unroll
            for (int j = 0; j < 8; j++)
#pragma unroll
                for (int c = 0; c < 4; c++) acc[i][j][c] = 0.f;

#pragma unroll
        for (int ks = 0; ks < 4; ks++) {
            unsigned af[2][4], bf[8][2];
#pragma unroll
            for (int i = 0; i < 2; i++) {
                const unsigned* p = Qu + (wq + 16 * i + gid) * 36 + ks * 8 + t4;
                af[i][0] = p[0]; af[i][1] = p[8 * 36]; af[i][2] = p[4]; af[i][3] = p[8 * 36 + 4];
            }
#pragma unroll
            for (int j = 0; j < 8; j++) {
                const unsigned* p = Kb + (wk + 8 * j + gid) * 36 + ks * 8 + t4;
                bf[j][0] = p[0]; bf[j][1] = p[4];
            }
#pragma unroll
            for (int i = 0; i < 2; i++)
#pragma unroll
                for (int j = 0; j < 8; j++) MMA_F16(acc[i][j], af[i], bf[j]);
        }

        // store S (+bias)
#pragma unroll
        for (int i = 0; i < 2; i++) {
            const int r0 = wq + 16 * i + gid;
#pragma unroll
            for (int j = 0; j < 8; j++) {
                const int col = wk + 8 * j + 2 * t4;      // within chunk
                const float2 b0 = *(const float2*)(bias + (size_t)(n0 + r0) * N_ + m0 + col);
                const float2 b1 = *(const float2*)(bias + (size_t)(n0 + r0 + 8) * N_ + m0 + col);
                S[r0 * 517 + m0 + col]           = acc[i][j][0] + b0.x;
                S[r0 * 517 + m0 + col + 1]       = acc[i][j][1] + b0.y;
                S[(r0 + 8) * 517 + m0 + col]     = acc[i][j][2] + b1.x;
                S[(r0 + 8) * 517 + m0 + col + 1] = acc[i][j][3] + b1.y;
            }
        }
    }
    __syncthreads();

    // ---- phase 2: exact row softmax; rewrite P as RNA tf32 ---------------
    {
#pragma unroll
        for (int ii = 0; ii < 8; ii++) {
            float*    row  = S  + (warp * 8 + ii) * 517;
            unsigned* rowu = Su + (warp * 8 + ii) * 517;
            float mx = -3.4e38f;
            for (int m = lane; m < N_; m += 32) mx = fmaxf(mx, row[m]);
#pragma unroll
            for (int o = 16; o; o >>= 1) mx = fmaxf(mx, __shfl_xor_sync(0xffffffffu, mx, o));
            float sum = 0.f;
            for (int m = lane; m < N_; m += 32) {
                const float e = __expf(row[m] - mx);
                row[m] = e;
                sum += e;
            }
#pragma unroll
            for (int o = 16; o; o >>= 1) sum += __shfl_xor_sync(0xffffffffu, sum, o);
            const float inv = 1.f / sum;
            for (int m = lane; m < N_; m += 32) rowu[m] = f2tf32(row[m] * inv);
        }
    }

    // ---- phase 3: O = P V (tf32, verified). warp = (q-half, 64-key split) -
    const int wq3 = (warp & 1) * 32;    // query tile base
    const int kg  = warp >> 1;          // 0..3: 64-key group within chunk
    float acc3[2][8][4];
#pragma unroll
    for (int i = 0; i < 2; i++)
#pragma unroll
        for (int j = 0; j < 8; j++)
#pragma unroll
            for (int c = 0; c < 4; c++) acc3[i][j][c] = 0.f;

    for (int ch = 0; ch < 2; ch++) {
        const int m0 = ch * 256;
        __syncthreads();
        // stage Vt[d][m] (transposed, RNA->tf32), stride 261
        for (int i = tid; i < 256 * 16; i += 256) {
            const int r = i >> 4, c = (i & 15) << 2;   // r = key, c = d
            const float4 vv = *(const float4*)(V + (rowbase + m0 + r) * D_ + headoff + c);
            STu[(c + 0) * 261 + r] = f2tf32(vv.x);
            STu[(c + 1) * 261 + r] = f2tf32(vv.y);
            STu[(c + 2) * 261 + r] = f2tf32(vv.z);
            STu[(c + 3) * 261 + r] = f2tf32(vv.w);
        }
        __syncthreads();

#pragma unroll
        for (int ks = 0; ks < 8; ks++) {
            unsigned af[2][4], bf[8][2];
#pragma unroll
            for (int i = 0; i < 2; i++) {
                const unsigned* p = Su + (wq3 + 16 * i + gid) * 517 + m0 + kg * 64 + ks * 8 + t4;
                af[i][0] = p[0]; af[i][1] = p[8 * 517]; af[i][2] = p[4]; af[i][3] = p[8 * 517 + 4];
            }
#pragma unroll
            for (int j = 0; j < 8; j++) {
                const unsigned* p = STu + (8 * j + gid) * 261 + kg * 64 + ks * 8 + t4;
                bf[j][0] = p[0]; bf[j][1] = p[4];
            }
#pragma unroll
            for (int i = 0; i < 2; i++)
#pragma unroll
                for (int j = 0; j < 8; j++) MMA_TF32(acc3[i][j], af[i], bf[j]);
        }
    }

    // reduce the 4 k-split partials through smem (reuse S region, stride 68)
    __syncthreads();
    {
        float* part = S + warp * (32 * 68);
#pragma unroll
        for (int i = 0; i < 2; i++) {
            const int r = 16 * i + gid;
#pragma unroll
            for (int j = 0; j < 8; j++) {
                const int c = 8 * j + 2 * t4;
                *(float2*)(part + r * 68 + c)       = make_float2(acc3[i][j][0], acc3[i][j][1]);
                *(float2*)(part + (r + 8) * 68 + c) = make_float2(acc3[i][j][2], acc3[i][j][3]);
            }
        }
    }
    __syncthreads();

    // sum over kg and write O (fp16)
    for (int i = tid; i < 64 * 16; i += 256) {
        const int q  = i >> 4, dc = (i & 15) << 2;
        const int mt = q >> 5, qi = q & 31;
        float4 o = make_float4(0.f, 0.f, 0.f, 0.f);
#pragma unroll
        for (int kg2 = 0; kg2 < 4; kg2++) {
            const float4 p = *(const float4*)(S + (kg2 * 2 + mt) * (32 * 68) + qi * 68 + dc);
            o.x += p.x; o.y += p.y; o.z += p.z; o.w += p.w;
        }
        __half2* op = (__half2*)(O + (rowbase + n0 + q) * D_ + headoff + dc);
        op[0] = __floats2half2_rn(o.x, o.y);
        op[1] = __floats2half2_rn(o.z, o.w);
    }
}

// ---------------------------------------------------------------------------
// Launch
// ---------------------------------------------------------------------------
extern "C" void kernel_launch(void* const* d_in, const int* in_sizes, int n_in,
                              void* d_out, int out_size) {
    (void)in_sizes; (void)n_in; (void)out_size;
    const float* x    = (const float*)d_in[0];
    const float* lap  = (const float*)d_in[1];
    const float* ne   = (const float*)d_in[2];
    const float* Wq   = (const float*)d_in[3];
    const float* bq   = (const float*)d_in[4];
    const float* Wk   = (const float*)d_in[5];
    const float* bk   = (const float*)d_in[6];
    const float* Wv   = (const float*)d_in[7];
    const float* bv   = (const float*)d_in[8];
    const float* Wo   = (const float*)d_in[9];
    const float* bo   = (const float*)d_in[10];
    const float* W1   = (const float*)d_in[11];
    const float* b1   = (const float*)d_in[12];
    const float* W2   = (const float*)d_in[13];
    const float* b2   = (const float*)d_in[14];
    const float* g1   = (const float*)d_in[15];
    const float* be1  = (const float*)d_in[16];
    const float* g2   = (const float*)d_in[17];
    const float* be2  = (const float*)d_in[18];
    const float* alp  = (const float*)d_in[19];
    const float* bet  = (const float*)d_in[20];
    float* out = (float*)d_out;

    float *v, *x1, *bias;
    __half *xnh, *hh, *aoh, *hidh, *qh, *kh;
    __half *wqh, *wkh, *wvh, *woh, *w1h, *w2h;
    cudaGetSymbolAddress((void**)&v,    g_v);
    cudaGetSymbolAddress((void**)&x1,   g_x1);
    cudaGetSymbolAddress((void**)&bias, g_bias);
    cudaGetSymbolAddress((void**)&xnh,  g_xnh);
    cudaGetSymbolAddress((void**)&hh,   g_hh);
    cudaGetSymbolAddress((void**)&aoh,  g_aoh);
    cudaGetSymbolAddress((void**)&hidh, g_hidh);
    cudaGetSymbolAddress((void**)&qh,   g_qh);
    cudaGetSymbolAddress((void**)&kh,   g_kh);
    cudaGetSymbolAddress((void**)&wqh,  g_wqh);
    cudaGetSymbolAddress((void**)&wkh,  g_wkh);
    cudaGetSymbolAddress((void**)&wvh,  g_wvh);
    cudaGetSymbolAddress((void**)&woh,  g_woh);
    cudaGetSymbolAddress((void**)&w1h,  g_w1h);
    cudaGetSymbolAddress((void**)&w2h,  g_w2h);

    cudaFuncSetAttribute(attn_tc,
                         cudaFuncAttributeMaxDynamicSharedMemorySize, ATT_SMEM);
    cudaFuncSetAttribute(gemm_qkv,
                         cudaFuncAttributeMaxDynamicSharedMemorySize, GEMM_SMEM);
    cudaFuncSetAttribute(gemm_tc<false, true, false>,
                         cudaFuncAttributeMaxDynamicSharedMemorySize, GEMM_SMEM);
    cudaFuncSetAttribute(gemm_tc<true, false, true>,
                         cudaFuncAttributeMaxDynamicSharedMemorySize, GEMM_SMEM);

    // 0) weights -> fp16
    cvt_f2h<<<256, 256>>>(Wq, wqh, D_ * D_ / 4);
    cvt_f2h<<<256, 256>>>(Wk, wkh, D_ * D_ / 4);
    cvt_f2h<<<256, 256>>>(Wv, wvh, D_ * D_ / 4);
    cvt_f2h<<<256, 256>>>(Wo, woh, D_ * D_ / 4);
    cvt_f2h<<<512, 256>>>(W1, w1h, DFF_ * D_ / 4);
    cvt_f2h<<<512, 256>>>(W2, w2h, D_ * DFF_ / 4);

    // 1) graph bias (b,t,k-invariant)
    bias_kernel<<<N_, N_>>>(ne, lap, alp, bet, bias);

    // 2) LN1 -> fp16
    ln_kernel<<<ROWS_, 128>>>(x, g1, be1, xnh);

    // 3) Q/K/V projections — fused single launch; Q,K fp16; V fp32
    const dim3 thr(256);
    QKVArgs qa;
    qa.W[0] = wqh; qa.W[1] = wkh; qa.W[2] = wvh;
    qa.b[0] = bq;  qa.b[1] = bk;  qa.b[2] = bv;
    qa.oh[0] = qh; qa.oh[1] = kh; qa.of = v;
    gemm_qkv<<<dim3(D_ / 128, ROWS_ / 128, 3), thr, GEMM_SMEM>>>(xnh, qa);

    // 4) attention (192 heads x 8 query tiles) -> fp16 ao
    attn_tc<<<dim3(N_ / 64, BT_ * KH_), thr, ATT_SMEM>>>(qh, kh, v, bias, aoh);

    // 5) output projection + residual (x) -> fp32 x1
    gemm_tc<false, true, false><<<dim3(D_ / 128, ROWS_ / 128), thr, GEMM_SMEM>>>(
        aoh, woh, bo, x, x1, D_, D_);

    // 6) LN2 -> fp16
    ln_kernel<<<ROWS_, 128>>>(x1, g2, be2, hh);

    // 7) FFN1 with fused ReLU -> fp16 hid
    gemm_tc<true, false, true><<<dim3(DFF_ / 128, ROWS_ / 128), thr, GEMM_SMEM>>>(
        hh, w1h, b1, nullptr, hidh, DFF_, D_);

    // 8) FFN2 + residual (x1) -> fp32 output
    gemm_tc<false, true, false><<<dim3(D_ / 128, ROWS_ / 128), thr, GEMM_SMEM>>>(
        hidh, w2h, b2, x1, out, D_, DFF_);
}